// round 1
// baseline (speedup 1.0000x reference)
#include <cuda_runtime.h>

// Scratch for cross-kernel communication (no allocations allowed).
__device__ float g_final_state[3];
__device__ int   g_fill_start_elem;  // first float element index the fill kernel must write

// ---------------------------------------------------------------------------
// Kernel A: exact sequential fp32 recurrence until bitwise fixed point.
//   inf = b*(S*I)/pop ; rec = g*I
//   nS = S - inf ; nI = (I + inf) - rec ; nR = R + rec
// Op order matches the JAX reference exactly (explicit __f*_rn intrinsics
// prevent FMA contraction, preserving bit-identical rounding).
// ---------------------------------------------------------------------------
__global__ void sir_scan_kernel(const float* __restrict__ x,
                                const float* __restrict__ bw,
                                const float* __restrict__ gw,
                                int steps,
                                float* __restrict__ out)
{
    if (blockIdx.x != 0 || threadIdx.x != 0) return;

    float S = x[0], I = x[1], R = x[2];
    float pop = __fadd_rn(__fadd_rn(x[0], x[1]), x[2]);
    const float b = bw[0];
    const float g = gw[0];
    const bool pop_is_one = (pop == 1.0f);   // division by 1.0f is exact -> skip it

    out[0] = S; out[1] = I; out[2] = R;

    int i = 1;
    if (pop_is_one) {
        for (; i < steps; ++i) {
            float inf = __fmul_rn(b, __fmul_rn(S, I));
            float rec = __fmul_rn(g, I);
            float nS  = __fsub_rn(S, inf);
            float nI  = __fsub_rn(__fadd_rn(I, inf), rec);
            float nR  = __fadd_rn(R, rec);
            out[3 * i + 0] = nS;
            out[3 * i + 1] = nI;
            out[3 * i + 2] = nR;
            bool conv = (nS == S) && (nI == I) && (nR == R);
            S = nS; I = nI; R = nR;
            if (conv) { ++i; break; }   // rows [0, i) are written; rest are constant
        }
    } else {
        for (; i < steps; ++i) {
            float inf = __fdiv_rn(__fmul_rn(b, __fmul_rn(S, I)), pop);
            float rec = __fmul_rn(g, I);
            float nS  = __fsub_rn(S, inf);
            float nI  = __fsub_rn(__fadd_rn(I, inf), rec);
            float nR  = __fadd_rn(R, rec);
            out[3 * i + 0] = nS;
            out[3 * i + 1] = nI;
            out[3 * i + 2] = nR;
            bool conv = (nS == S) && (nI == I) && (nR == R);
            S = nS; I = nI; R = nR;
            if (conv) { ++i; break; }
        }
    }

    g_final_state[0] = S;
    g_final_state[1] = I;
    g_final_state[2] = R;
    g_fill_start_elem = 3 * i;   // i == steps if no convergence -> nothing to fill
}

// ---------------------------------------------------------------------------
// Kernel B: broadcast the fixed-point state into all remaining rows.
// Element-indexed for perfectly coalesced 32-bit stores.
// ---------------------------------------------------------------------------
__global__ void sir_fill_kernel(float* __restrict__ out, int total_elems)
{
    const int start = g_fill_start_elem;
    const float v0 = g_final_state[0];
    const float v1 = g_final_state[1];
    const float v2 = g_final_state[2];

    int e = start + blockIdx.x * blockDim.x + threadIdx.x;
    const int stride = gridDim.x * blockDim.x;
    for (; e < total_elems; e += stride) {
        int m = e % 3;
        out[e] = (m == 0) ? v0 : ((m == 1) ? v1 : v2);
    }
}

extern "C" void kernel_launch(void* const* d_in, const int* in_sizes, int n_in,
                              void* d_out, int out_size)
{
    const float* x  = (const float*)d_in[0];
    const float* bw = (const float*)d_in[1];
    const float* gw = (const float*)d_in[2];
    float* out = (float*)d_out;

    const int steps = out_size / 3;
    const int total_elems = out_size;

    sir_scan_kernel<<<1, 1>>>(x, bw, gw, steps, out);

    int threads = 256;
    int blocks = (total_elems + threads - 1) / threads;
    if (blocks > 65535 * 8) blocks = 65535 * 8;  // safety clamp; grid-stride covers rest
    sir_fill_kernel<<<blocks, threads>>>(out, total_elems);
}

// round 2
// speedup vs baseline: 2.6519x; 2.6519x over previous
#include <cuda_runtime.h>

// Cross-kernel scratch (no allocations allowed).
__device__ float g_final_state[3];
__device__ int   g_fill_start_elem;   // first float element index for the fill kernel (multiple of 12, or == total)

// ---------------------------------------------------------------------------
// Kernel A: sequential SIR recurrence, single thread.
// Fast FMA formulation (algebraically identical, single-rounding per value):
//   u  = 1 - g + b'*S          (b' = b/pop)
//   nI = I*u                    == I + b'*S*I - g*I
//   nS = fma(-b'*I, S, S)       == S - b'*(S*I)
//   nR = fma(g, I, R)           == R + g*I
// Chain = 8 cyc/iter. Rows written 4 at a time via 3x STG.128.
// Convergence detected per 4-chunk (bitwise state equality), confirmed with a
// one-step fixed-point check (excludes period-2/4 cycles).
// ---------------------------------------------------------------------------
__global__ void sir_scan_kernel(const float* __restrict__ x,
                                const float* __restrict__ bw,
                                const float* __restrict__ gw,
                                int steps,
                                float* __restrict__ out)
{
    if (blockIdx.x != 0 || threadIdx.x != 0) return;

    float S = x[0], I = x[1], R = x[2];
    const float pop  = __fadd_rn(__fadd_rn(x[0], x[1]), x[2]);
    const float g    = gw[0];
    const float beff = (pop == 1.0f) ? bw[0] : __fdiv_rn(bw[0], pop);
    const float omg  = __fsub_rn(1.0f, g);   // 1 - g

    // Row 0 = initial condition.
    out[0] = S; out[1] = I; out[2] = R;

    int i = 1;

    // Head: rows 1..3 scalar, so the chunked loop starts at i=4 (i%4==0,
    // making every chunk's first element offset 3*i a multiple of 12 -> 16B aligned).
    for (int h = 0; h < 3 && i < steps; ++h, ++i) {
        float u  = __fmaf_rn(beff, S, omg);
        float v  = __fmul_rn(beff, I);
        float nI = __fmul_rn(I, u);
        float nS = __fmaf_rn(-v, S, S);
        float nR = __fmaf_rn(g, I, R);
        S = nS; I = nI; R = nR;
        out[3 * i + 0] = S;
        out[3 * i + 1] = I;
        out[3 * i + 2] = R;
    }

    bool converged = false;

    for (; i + 4 <= steps; i += 4) {
        const float S0 = S, I0 = I, R0 = R;
        float r[12];
        #pragma unroll
        for (int k = 0; k < 4; ++k) {
            float u  = __fmaf_rn(beff, S, omg);
            float v  = __fmul_rn(beff, I);
            float nI = __fmul_rn(I, u);
            float nS = __fmaf_rn(-v, S, S);
            float nR = __fmaf_rn(g, I, R);
            S = nS; I = nI; R = nR;
            r[3 * k + 0] = S;
            r[3 * k + 1] = I;
            r[3 * k + 2] = R;
        }
        float4* p = reinterpret_cast<float4*>(out + 3 * i);   // 3*i % 12 == 0 -> 16B aligned
        p[0] = make_float4(r[0], r[1],  r[2],  r[3]);
        p[1] = make_float4(r[4], r[5],  r[6],  r[7]);
        p[2] = make_float4(r[8], r[9],  r[10], r[11]);

        if (S == S0 && I == I0 && R == R0) {
            // Confirm a true period-1 fixed point before declaring the tail constant.
            float u  = __fmaf_rn(beff, S, omg);
            float v  = __fmul_rn(beff, I);
            float nI = __fmul_rn(I, u);
            float nS = __fmaf_rn(-v, S, S);
            float nR = __fmaf_rn(g, I, R);
            if (nS == S && nI == I && nR == R) {
                i += 4;                 // rows [0, i) are written
                converged = true;
                break;
            }
        }
    }

    if (!converged) {
        // Tail (< 4 rows) if the chunked loop exhausted without convergence.
        for (; i < steps; ++i) {
            float u  = __fmaf_rn(beff, S, omg);
            float v  = __fmul_rn(beff, I);
            float nI = __fmul_rn(I, u);
            float nS = __fmaf_rn(-v, S, S);
            float nR = __fmaf_rn(g, I, R);
            S = nS; I = nI; R = nR;
            out[3 * i + 0] = S;
            out[3 * i + 1] = I;
            out[3 * i + 2] = R;
        }
    }

    g_final_state[0] = S;
    g_final_state[1] = I;
    g_final_state[2] = R;
    g_fill_start_elem = 3 * i;   // multiple of 12 when converged; == total otherwise
}

// ---------------------------------------------------------------------------
// Kernel B: broadcast fixed point into the tail. One 12-element group
// (= full pattern period = 48B) per thread iteration: 3x STG.128, no modulo.
// ---------------------------------------------------------------------------
__global__ void sir_fill_kernel(float* __restrict__ out, int total_elems)
{
    const int start = g_fill_start_elem;          // multiple of 12 (or == total)
    const float v0 = g_final_state[0];
    const float v1 = g_final_state[1];
    const float v2 = g_final_state[2];

    const float4 p0 = make_float4(v0, v1, v2, v0);
    const float4 p1 = make_float4(v1, v2, v0, v1);
    const float4 p2 = make_float4(v2, v0, v1, v2);

    const int groups = (total_elems - start) / 12;
    const int stride = gridDim.x * blockDim.x;

    for (int gdx = blockIdx.x * blockDim.x + threadIdx.x; gdx < groups; gdx += stride) {
        float4* p = reinterpret_cast<float4*>(out + start + 12 * gdx);
        p[0] = p0;
        p[1] = p1;
        p[2] = p2;
    }

    // Remainder (< 12 elems) — only possible if total_elems % 12 != 0.
    if (blockIdx.x == 0 && threadIdx.x == 0) {
        for (int e = start + 12 * groups; e < total_elems; ++e) {
            int m = e % 3;   // start % 3 == 0, so absolute index works
            out[e] = (m == 0) ? v0 : ((m == 1) ? v1 : v2);
        }
    }
}

extern "C" void kernel_launch(void* const* d_in, const int* in_sizes, int n_in,
                              void* d_out, int out_size)
{
    const float* x  = (const float*)d_in[0];
    const float* bw = (const float*)d_in[1];
    const float* gw = (const float*)d_in[2];
    float* out = (float*)d_out;

    const int steps = out_size / 3;

    sir_scan_kernel<<<1, 1>>>(x, bw, gw, steps, out);

    const int threads   = 256;
    const int maxGroups = out_size / 12 + 1;
    int blocks = (maxGroups + threads - 1) / threads;
    sir_fill_kernel<<<blocks, threads>>>(out, out_size);
}

// round 3
// speedup vs baseline: 7.8502x; 2.9602x over previous
#include <cuda_runtime.h>
#include <math.h>

// Cross-kernel scratch (no allocations allowed).
__device__ float  g_S, g_Irec, g_Rinf, g_A, g_g;
__device__ double g_c;        // log2(u), u = 1 - g + beff*S_frozen
__device__ int    g_r;        // row index of the recorded state (last row the scan wrote)
__device__ int    g_cut;      // first row of the constant region (multiple of 4), <= steps

// ---------------------------------------------------------------------------
// Kernel A: serial scan ONLY until S is bitwise frozen (monotone => permanent).
//   u  = 1 - g + beff*S ;  nI = I*u ;  nS = fma(-beff*I, S, S) ;  nR = fma(g,I,R)
// Once S is unchanged across a 4-step chunk and u < 1 (so I keeps shrinking),
// S and u are frozen forever: the remaining trajectory has a closed form.
// Fallback: if no freeze (or u >= 1), scan serially to the end (always correct).
// ---------------------------------------------------------------------------
__global__ void sir_scan_kernel(const float* __restrict__ x,
                                const float* __restrict__ bw,
                                const float* __restrict__ gw,
                                int steps,
                                float* __restrict__ out)
{
    if (blockIdx.x != 0 || threadIdx.x != 0) return;

    float S = x[0], I = x[1], R = x[2];
    const float pop  = __fadd_rn(__fadd_rn(x[0], x[1]), x[2]);
    const float g    = gw[0];
    const float beff = (pop == 1.0f) ? bw[0] : __fdiv_rn(bw[0], pop);
    const float omg  = __fsub_rn(1.0f, g);

    out[0] = S; out[1] = I; out[2] = R;

    int i = 1;
    // Head rows 1..3 so chunks start at i=4 (3*i % 12 == 0 -> 16B-aligned float4s).
    for (int h = 0; h < 3 && i < steps; ++h, ++i) {
        float u  = __fmaf_rn(beff, S, omg);
        float v  = __fmul_rn(beff, I);
        float nI = __fmul_rn(I, u);
        float nS = __fmaf_rn(-v, S, S);
        float nR = __fmaf_rn(g, I, R);
        S = nS; I = nI; R = nR;
        out[3*i] = S; out[3*i+1] = I; out[3*i+2] = R;
    }

    bool frozen = false;
    for (; i + 4 <= steps; i += 4) {
        const float S0 = S;
        float r[12];
        #pragma unroll
        for (int k = 0; k < 4; ++k) {
            float u  = __fmaf_rn(beff, S, omg);
            float v  = __fmul_rn(beff, I);
            float nI = __fmul_rn(I, u);
            float nS = __fmaf_rn(-v, S, S);
            float nR = __fmaf_rn(g, I, R);
            S = nS; I = nI; R = nR;
            r[3*k] = S; r[3*k+1] = I; r[3*k+2] = R;
        }
        float4* p = reinterpret_cast<float4*>(out + 3 * i);
        p[0] = make_float4(r[0], r[1],  r[2],  r[3]);
        p[1] = make_float4(r[4], r[5],  r[6],  r[7]);
        p[2] = make_float4(r[8], r[9],  r[10], r[11]);

        if (S == S0) {
            float u = __fmaf_rn(beff, S, omg);
            if (u < 1.0f && u > 0.0f) {   // contracting: S frozen permanently
                i += 4;                    // rows [0, i) written; state = row i-1
                frozen = true;
                break;
            }
        }
    }

    if (!frozen) {
        // Fallback: finish serially (tail < 4 rows, or genuinely non-contracting case).
        for (; i < steps; ++i) {
            float u  = __fmaf_rn(beff, S, omg);
            float v  = __fmul_rn(beff, I);
            float nI = __fmul_rn(I, u);
            float nS = __fmaf_rn(-v, S, S);
            float nR = __fmaf_rn(g, I, R);
            S = nS; I = nI; R = nR;
            out[3*i] = S; out[3*i+1] = I; out[3*i+2] = R;
        }
        g_r = steps - 1;
        g_cut = steps;           // B1/B2 have nothing to do
        g_S = S; g_Irec = I; g_Rinf = R; g_A = 0.0f; g_g = g; g_c = 0.0;
        return;
    }

    const int r_row = i - 1;     // recorded state row
    const float  u  = __fmaf_rn(beff, S, omg);
    const double ud = (double)u;
    const double c  = log2(ud);                       // < 0
    const double Ad = (double)g * (double)I / (1.0 - ud);
    const double Rinf = (double)R + Ad;

    // First row where both I and the R-deficit have underflown to irrelevance:
    // u^t < 2^-160 / max(I, A)  =>  t > (160 + log2(max)) / (-c)
    double mx = fmax((double)I, Ad);
    if (mx < 1e-300) mx = 1e-300;
    double t_d = (160.0 + log2(mx)) / (-c);
    long long cut_ll = r_row + (long long)(t_d) + 8;
    long long cut4   = ((cut_ll + 3) / 4) * 4;        // multiple of 4 -> 3*cut % 12 == 0
    int cut = (cut4 > (long long)steps) ? steps : (int)cut4;

    g_r    = r_row;
    g_cut  = cut;
    g_S    = S;
    g_Irec = I;
    g_A    = (float)Ad;
    g_Rinf = (float)Rinf;
    g_g    = g;
    g_c    = c;
}

// ---------------------------------------------------------------------------
// Kernel B1: transition rows (g_r, g_cut) via closed form.
//   m = k - r ;  p = 2^(m*c) ;  I = Irec*p ;  R = Rinf - A*p ;  S = S_frozen
// Small row count (~10-20k typically); scalar stores are fine.
// ---------------------------------------------------------------------------
__global__ void sir_closed_form_kernel(float* __restrict__ out)
{
    const int r   = g_r;
    const int cut = g_cut;
    const float  S    = g_S;
    const float  Irec = g_Irec;
    const float  A    = g_A;
    const float  Rinf = g_Rinf;
    const double c    = g_c;

    const int n = cut - r - 1;           // rows r+1 .. cut-1
    if (n <= 0) return;

    const int stride = gridDim.x * blockDim.x;
    for (int idx = blockIdx.x * blockDim.x + threadIdx.x; idx < n; idx += stride) {
        const int m = idx + 1;           // steps past recorded state
        const float p = exp2f((float)((double)m * c));
        const int k = r + m;
        out[3*k + 0] = S;
        out[3*k + 1] = __fmul_rn(Irec, p);
        out[3*k + 2] = __fmaf_rn(-A, p, Rinf);
    }
}

// ---------------------------------------------------------------------------
// Kernel B2: constant region [g_cut, steps): (S, 0, Rinf).
// One float4 per thread, fully coalesced. 3*cut % 12 == 0, so the absolute
// float4 index j has pattern phase j % 3.
// ---------------------------------------------------------------------------
__global__ void sir_fill_kernel(float* __restrict__ out, int total_elems)
{
    const float v0 = g_S;
    const float v1 = 0.0f;
    const float v2 = g_Rinf;

    const float4 p0 = make_float4(v0, v1, v2, v0);
    const float4 p1 = make_float4(v1, v2, v0, v1);
    const float4 p2 = make_float4(v2, v0, v1, v2);

    const int start4 = (3 * g_cut) / 4;              // multiple of 3
    const int n4     = total_elems / 4;
    const int stride = gridDim.x * blockDim.x;

    for (int j = start4 + blockIdx.x * blockDim.x + threadIdx.x; j < n4; j += stride) {
        const int ph = j % 3;
        float4 v = (ph == 0) ? p0 : ((ph == 1) ? p1 : p2);
        reinterpret_cast<float4*>(out)[j] = v;
    }

    // Scalar remainder if total_elems % 4 != 0 (not hit for steps = 4M).
    if (blockIdx.x == 0 && threadIdx.x == 0) {
        for (int e = n4 * 4; e < total_elems; ++e) {
            if (e >= 3 * g_cut) {
                int m = e % 3;
                out[e] = (m == 0) ? v0 : ((m == 1) ? v1 : v2);
            }
        }
    }
}

extern "C" void kernel_launch(void* const* d_in, const int* in_sizes, int n_in,
                              void* d_out, int out_size)
{
    const float* x  = (const float*)d_in[0];
    const float* bw = (const float*)d_in[1];
    const float* gw = (const float*)d_in[2];
    float* out = (float*)d_out;

    const int steps = out_size / 3;

    sir_scan_kernel<<<1, 1>>>(x, bw, gw, steps, out);

    // B1: grid-stride over the (unknown-at-host) transition range.
    sir_closed_form_kernel<<<128, 256>>>(out);

    // B2: enough threads for the whole float4 range; early threads before cut exit
    // via the loop bound (they start past start4 only if in range).
    const int threads = 256;
    int blocks = (out_size / 4 + threads - 1) / threads;
    if (blocks < 1) blocks = 1;
    sir_fill_kernel<<<blocks, threads>>>(out, out_size);
}